// round 10
// baseline (speedup 1.0000x reference)
#include <cuda_runtime.h>
#include <math.h>
#include <stdint.h>

#define KMAX 64
#define BUF  16
#define NLVL 5          // levels 3..7
#define NB   (NLVL * KMAX)
#define NAS  148        // assign grid
#define NTHR 1024
#define FULLM 0xffffffffu

// ---------------- device-global state (zero-init; g_best restored by k_final) ----------------
__device__ unsigned long long g_best[2][NB];     // INVERTED packed keys; 0 = empty (max-reduced)
__device__ int    g_k2b[KMAX];                   // original k -> bucket slot (written by assign blk 0)
__device__ int    g_cnt01[2];
__device__ double g_blk_lse[NAS];
__device__ double g_corr_val;
__device__ double g_task_gl[2][KMAX];
__device__ double g_task_oob[2][KMAX];

__device__ __forceinline__ float f_inf() { return __int_as_float(0x7f800000); }

// Non-FMA cross product: matches XLA's unfused mul/sub semantics exactly.
__device__ __forceinline__ float cross_nf(float ax, float ay, float bx, float by)
{
    return __fsub_rn(__fmul_rn(ax, by), __fmul_rn(ay, bx));
}

// ---------------- geometry helpers (bit-identical to prior passing rounds) ----------------
__device__ float shoelace16(const float2* V, int c)
{
    float s = 0.f;
    #pragma unroll
    for (int i = 0; i < BUF; i++) {
        if (i >= c) continue;
        int nxt = (i + 1 < c) ? i + 1 : 0;
        s = __fadd_rn(s, cross_nf(V[i].x, V[i].y, V[nxt].x, V[nxt].y));
    }
    return 0.5f * fabsf(s);
}

__device__ __forceinline__ int hull_member_warp(const float2* pts, int n, int i, int lane)
{
    bool flag = false;
    if (lane < n && lane != i) {
        float pix = pts[i].x, piy = pts[i].y;
        float dx = __fsub_rn(pts[lane].x, pix), dy = __fsub_rn(pts[lane].y, piy);
        float mn = f_inf();
        for (int k = 0; k < n; k++) {
            float cr = cross_nf(dx, dy, __fsub_rn(pts[k].x, pix), __fsub_rn(pts[k].y, piy));
            mn = fminf(mn, cr);
        }
        flag = (mn >= -1e-6f);
    }
    return __ballot_sync(FULLM, flag) != 0;
}

__device__ int hull_finish_warp(const float2* pts, int n, const int* hflag,
                                float* skey, float2* sV, int lane)
{
    bool hf = (lane < n) ? (hflag[lane] != 0) : false;
    unsigned mask = __ballot_sync(FULLM, hf);
    int cnt = __popc(mask);
    float sx = 0.f, sy = 0.f;
    for (int i = 0; i < n; i++)
        if ((mask >> i) & 1) { sx = __fadd_rn(sx, pts[i].x); sy = __fadd_rn(sy, pts[i].y); }
    float cd = (float)(cnt > 0 ? cnt : 1);
    float cenx = __fdiv_rn(sx, cd), ceny = __fdiv_rn(sy, cd);
    if (lane < n)
        skey[lane] = hf ? atan2f(__fsub_rn(pts[lane].y, ceny), __fsub_rn(pts[lane].x, cenx))
                        : f_inf();
    __syncwarp();
    if (lane < n) {
        float ki = skey[lane];
        int r = 0;
        for (int j = 0; j < n; j++) {
            float kj = skey[j];
            r += (kj < ki) || (kj == ki && j < lane);   // stable rank == argsort
        }
        sV[r] = pts[lane];
    }
    if (lane >= n && lane < BUF) sV[lane] = make_float2(0.f, 0.f);
    __syncwarp();
    return cnt;
}

__device__ void clip_warp(float2* V, int& c, float2 a, float2 b, int lane, float2* scratch)
{
    float ex = __fsub_rn(b.x, a.x), ey = __fsub_rn(b.y, a.y);
    int cc = c;
    bool active = (lane < BUF) && (lane < cc);
    int nxt = (lane + 1 < cc) ? lane + 1 : 0;
    float2 cur = active ? V[lane] : make_float2(0.f, 0.f);
    float2 nx  = active ? V[nxt]  : make_float2(0.f, 0.f);
    float s_cur = cross_nf(ex, ey, __fsub_rn(cur.x, a.x), __fsub_rn(cur.y, a.y));
    float s_nxt = cross_nf(ex, ey, __fsub_rn(nx.x,  a.x), __fsub_rn(nx.y,  a.y));
    bool in_cur = s_cur >= 0.f, in_nxt = s_nxt >= 0.f;
    float den = __fsub_rn(s_cur, s_nxt);
    float t = (fabsf(den) > 1e-9f) ? __fdiv_rn(s_cur, den) : 0.f;
    float2 ipt = make_float2(__fadd_rn(cur.x, __fmul_rn(t, __fsub_rn(nx.x, cur.x))),
                             __fadd_rn(cur.y, __fmul_rn(t, __fsub_rn(nx.y, cur.y))));
    bool f_int = active && (in_cur != in_nxt);
    bool f_nxt = active && in_nxt;
    unsigned bi = __ballot_sync(FULLM, f_int);
    unsigned bn = __ballot_sync(FULLM, f_nxt);
    unsigned below = (1u << lane) - 1u;
    int pos_i = __popc(bi & below) + __popc(bn & below);
    int pos_n = pos_i + (f_int ? 1 : 0);
    int nc = __popc(bi) + __popc(bn);
    __syncwarp();
    if (f_int && pos_i < BUF) scratch[pos_i] = ipt;
    if (f_nxt && pos_n < BUF) scratch[pos_n] = nx;
    __syncwarp();
    if (lane < BUF) V[lane] = (lane < nc) ? scratch[lane] : make_float2(0.f, 0.f);
    __syncwarp();
    c = nc;
}

// ================= kernel 1: prep + assign + cls logsumexp =================
__global__ void __launch_bounds__(NTHR, 1) k_assign(
    const float* __restrict__ rpi, const float* __restrict__ rpr,
    const float* __restrict__ cls, const float* __restrict__ pstr,
    const float* __restrict__ gtb, int N, int K)
{
    __shared__ float  s_cx[KMAX], s_cy[KMAX], s_rw[KMAX], s_rh[KMAX];
    __shared__ int    s_lvl[KMAX];
    __shared__ float4 s_bkt[NB];
    __shared__ int    s_k2b[KMAX];
    __shared__ int    s_cnt[NLVL];
    __shared__ unsigned long long sb0[NB], sb1[NB];
    __shared__ double s_red[32];

    const int tid  = threadIdx.x;
    const int bid  = blockIdx.x;
    const int lane = tid & 31;
    const int w    = tid >> 5;

    for (int q = tid; q < NB; q += NTHR) { sb0[q] = 0ull; sb1[q] = 0ull; }
    if (tid < K) {
        const float* r = gtb + 8 * tid;
        float xmn = fminf(fminf(r[0], r[2]), fminf(r[4], r[6]));
        float xmx = fmaxf(fmaxf(r[0], r[2]), fmaxf(r[4], r[6]));
        float ymn = fminf(fminf(r[1], r[3]), fminf(r[5], r[7]));
        float ymx = fmaxf(fmaxf(r[1], r[3]), fmaxf(r[5], r[7]));
        float ww = fmaxf(__fsub_rn(xmx, xmn), 1e-6f);
        float hh = fmaxf(__fsub_rn(ymx, ymn), 1e-6f);
        s_cx[tid] = __fmul_rn(__fadd_rn(xmn, xmx), 0.5f);
        s_cy[tid] = __fmul_rn(__fadd_rn(ymn, ymx), 0.5f);
        s_rw[tid] = __fdiv_rn(1.0f, ww);
        s_rh[tid] = __fdiv_rn(1.0f, hh);
        float lv = __fmul_rn(__fadd_rn(log2f(__fdiv_rn(ww, 4.0f)),
                                       log2f(__fdiv_rn(hh, 4.0f))), 0.5f);
        int lvl = (int)lv;
        s_lvl[tid] = max(3, min(7, lvl));
    }
    __syncthreads();
    if (tid == 0) {                                  // serial bucket build, ascending k
        int cnt[NLVL];
        #pragma unroll
        for (int l = 0; l < NLVL; l++) cnt[l] = 0;
        for (int q = 0; q < K; q++) {
            int li = s_lvl[q] - 3;
            int slot = li * KMAX + cnt[li];
            s_bkt[slot] = make_float4(s_cx[q], s_cy[q], s_rw[q], s_rh[q]);
            s_k2b[q] = slot;
            cnt[li]++;
        }
        #pragma unroll
        for (int l = 0; l < NLVL; l++) s_cnt[l] = cnt[l];
    }
    __syncthreads();
    if (bid == 0 && tid < K) g_k2b[tid] = s_k2b[tid];   // publish map for k_tasks

    double lterm = 0.0;
    for (int n = bid * NTHR + tid; n - tid < N; n += NAS * NTHR) {
        bool act = (n < N);
        int li = 0;
        float2 pi = make_float2(0.f, 0.f), pr = make_float2(0.f, 0.f);
        if (act) {
            li = (31 - __clz((int)pstr[n])) - 3;     // stride is an exact power of two
            pi = __ldg((const float2*)(rpi + (size_t)n * 18 + 8));
            pr = __ldg((const float2*)(rpr + (size_t)n * 18 + 8));
        }
        unsigned un = (unsigned)n;
        unsigned actmask = __ballot_sync(FULLM, act);
        if (actmask) {
            int src = __ffs(actmask) - 1;
            int uli = __shfl_sync(FULLM, li, src);
            bool uniform = __all_sync(FULLM, !act || (li == uli));
            if (uniform) {
                int cnt = s_cnt[uli], base = uli * KMAX;
                for (int m = 0; m < cnt; m++) {
                    int slot = base + m;
                    float4 gq = s_bkt[slot];
                    unsigned long long ki = 0ull, kr = 0ull;
                    if (act) {
                        float dxi = __fmul_rn(__fsub_rn(pi.x, gq.x), gq.z);
                        float dyi = __fmul_rn(__fsub_rn(pi.y, gq.y), gq.w);
                        float ddi = __fadd_rn(__fmul_rn(dxi, dxi), __fmul_rn(dyi, dyi));
                        ki = ~(((unsigned long long)__float_as_uint(ddi) << 32) | un);
                        float dxr = __fmul_rn(__fsub_rn(pr.x, gq.x), gq.z);
                        float dyr = __fmul_rn(__fsub_rn(pr.y, gq.y), gq.w);
                        float ddr = __fadd_rn(__fmul_rn(dxr, dxr), __fmul_rn(dyr, dyr));
                        kr = ~(((unsigned long long)__float_as_uint(ddr) << 32) | un);
                    }
                    #pragma unroll
                    for (int o = 16; o; o >>= 1) {
                        unsigned long long ti = __shfl_down_sync(FULLM, ki, o);
                        unsigned long long tr = __shfl_down_sync(FULLM, kr, o);
                        if (ti > ki) ki = ti;
                        if (tr > kr) kr = tr;
                    }
                    if (lane == 0) {
                        if (ki > sb0[slot]) atomicMax(&sb0[slot], ki);
                        if (kr > sb1[slot]) atomicMax(&sb1[slot], kr);
                    }
                }
            } else if (act) {
                int cnt = s_cnt[li], base = li * KMAX;
                for (int m = 0; m < cnt; m++) {
                    int slot = base + m;
                    float4 gq = s_bkt[slot];
                    float dxi = __fmul_rn(__fsub_rn(pi.x, gq.x), gq.z);
                    float dyi = __fmul_rn(__fsub_rn(pi.y, gq.y), gq.w);
                    float ddi = __fadd_rn(__fmul_rn(dxi, dxi), __fmul_rn(dyi, dyi));
                    unsigned long long ki = ~(((unsigned long long)__float_as_uint(ddi) << 32) | un);
                    if (ki > sb0[slot]) atomicMax(&sb0[slot], ki);
                    float dxr = __fmul_rn(__fsub_rn(pr.x, gq.x), gq.z);
                    float dyr = __fmul_rn(__fsub_rn(pr.y, gq.y), gq.w);
                    float ddr = __fadd_rn(__fmul_rn(dxr, dxr), __fmul_rn(dyr, dyr));
                    unsigned long long kr = ~(((unsigned long long)__float_as_uint(ddr) << 32) | un);
                    if (kr > sb1[slot]) atomicMax(&sb1[slot], kr);
                }
            }
        }
        if (act) {
            const float4* c4 = (const float4*)(cls + (size_t)n * 16);
            float v[16];
            #pragma unroll
            for (int j = 0; j < 4; j++) {
                float4 f = __ldg(c4 + j);
                v[4 * j] = f.x; v[4 * j + 1] = f.y; v[4 * j + 2] = f.z; v[4 * j + 3] = f.w;
            }
            float mm = v[0];
            #pragma unroll
            for (int j = 1; j < 16; j++) mm = fmaxf(mm, v[j]);
            float ss = 0.f;
            #pragma unroll
            for (int j = 0; j < 16; j++) ss += __expf(v[j] - mm);
            lterm += (double)((mm + __logf(ss)) - v[0]);
        }
    }
    for (int o = 16; o; o >>= 1) lterm += __shfl_down_sync(FULLM, lterm, o);
    if (lane == 0) s_red[w] = lterm;
    __syncthreads();
    if (tid == 0) {
        double bs = 0.0;
        for (int q = 0; q < NTHR / 32; q++) bs += s_red[q];
        g_blk_lse[bid] = bs;
    }
    for (int q = tid; q < NB; q += NTHR) {
        if (sb0[q]) atomicMax(&g_best[0][q], sb0[q]);
        if (sb1[q]) atomicMax(&g_best[1][q], sb1[q]);
    }
}

// ================= kernel 2: per-block replay + corr + geometry =================
__global__ void __launch_bounds__(NTHR, 1) k_tasks(
    const float* __restrict__ rpi, const float* __restrict__ rpr,
    const float* __restrict__ cls, const float* __restrict__ gtb,
    const int* __restrict__ glab, int K)
{
    __shared__ unsigned long long s_cmp[KMAX];
    __shared__ int s_j[KMAX];
    __shared__ int s_lead[KMAX];
    __shared__ int s_pidx[KMAX], s_pgt[KMAX];
    __shared__ int s_npos;
    __shared__ double s_red[32];
    __shared__ float2 sP9[9];
    __shared__ float2 sGT[4];
    __shared__ float2 sG[4];
    __shared__ float2 sPtsB[13];
    __shared__ int    sHa[9], sHb[13];
    __shared__ float2 sVa[BUF], sVb[BUF];
    __shared__ float2 sScrA[BUF];
    __shared__ float  sKeyA[13], sKeyB[13], sKeyG[4];
    __shared__ float  s_apred, s_agt, s_aint, s_ahull, s_oob;

    const int tid  = threadIdx.x;
    const int bid  = blockIdx.x;
    const int lane = tid & 31;
    const int w    = tid >> 5;
    const int s = (bid >= KMAX) ? 1 : 0;
    const int m = bid - s * KMAX;

    // replay stage s (order-independent reformulation, validated rounds 6-9)
    if (tid < KMAX) {
        unsigned long long v = (tid < K) ? __ldcg(&g_best[s][__ldg(&g_k2b[tid])]) : 0ull;
        bool valid = (v != 0ull);
        unsigned long long pk = ~v;              // (md_bits<<32)|point_idx
        s_j[tid]   = valid ? (int)(unsigned)(pk & 0xffffffffu) : (-1 - tid);
        s_cmp[tid] = valid ? (((pk >> 32) << 32) | (unsigned)tid) : ~0ull;
    }
    __syncthreads();
    if (tid < KMAX) {
        int j = s_j[tid];
        bool lead = (j >= 0);
        if (lead)
            for (int e = 0; e < tid; e++)
                if (s_j[e] == j) { lead = false; break; }
        s_lead[tid] = lead ? 1 : 0;
    }
    __syncthreads();
    if (tid < K && s_lead[tid]) {
        int j = s_j[tid];
        unsigned long long best = s_cmp[tid];
        for (int e = 0; e < K; e++)
            if (s_j[e] == j && s_cmp[e] < best) best = s_cmp[e];
        int pos = 0;
        for (int e = 0; e < tid; e++) pos += s_lead[e];
        s_pidx[pos] = j;
        s_pgt[pos]  = (int)(unsigned)(best & 0xffffffffu);
    }
    __syncthreads();
    if (tid == 0) {
        int cnt = 0;
        for (int e = 0; e < K; e++) cnt += s_lead[e];
        s_npos = cnt;
        if (m == 0) g_cnt01[s] = cnt;            // blocks 0 and KMAX publish counts
    }
    __syncthreads();

    // block KMAX (stage 1, m==0): cls label correction, overlapped with geometry
    if (bid == KMAX) {
        double part = 0.0;
        if (tid < s_npos) {
            int j   = s_pidx[tid];
            int lab = glab[s_pgt[tid]];
            part = (double)cls[(size_t)j * 16 + 0] - (double)cls[(size_t)j * 16 + lab];
        }
        for (int o = 16; o; o >>= 1) part += __shfl_down_sync(FULLM, part, o);
        if (lane == 0) s_red[w] = part;
        __syncthreads();
        if (tid == 0) {
            double cs = 0.0;
            for (int q = 0; q < NTHR / 32; q++) cs += s_red[q];
            g_corr_val = cs;
        }
    }

    if (m >= s_npos) return;

    const float* rp  = s ? rpr : rpi;
    {
        int j  = s_pidx[m];
        int gi = s_pgt[m];
        const float* g8  = gtb + 8 * gi;
        const float* p18 = rp + (size_t)j * 18;
        if (tid < 4) {
            float2 c = make_float2(g8[2 * tid], g8[2 * tid + 1]);
            sGT[tid] = c;
            sPtsB[tid] = c;
        }
        if (tid >= 4 && tid < 13) {
            float2 c = make_float2(p18[2 * (tid - 4)], p18[2 * (tid - 4) + 1]);
            sP9[tid - 4] = c;
            sPtsB[tid] = c;
        }
    }
    __syncthreads();

    if (w < 13) {
        int h = hull_member_warp(sPtsB, 13, w, lane);
        if (lane == 0) sHb[w] = h;
    } else if (w >= 16 && w < 25) {
        int h = hull_member_warp(sP9, 9, w - 16, lane);
        if (lane == 0) sHa[w - 16] = h;
    } else if (w == 13) {
        if (lane < 4) {
            float cmx = (sGT[0].x + sGT[1].x + sGT[2].x + sGT[3].x) * 0.25f;
            float cmy = (sGT[0].y + sGT[1].y + sGT[2].y + sGT[3].y) * 0.25f;
            sKeyG[lane] = atan2f(__fsub_rn(sGT[lane].y, cmy),
                                 __fsub_rn(sGT[lane].x, cmx));
        }
        __syncwarp();
        if (lane < 4) {
            float ki = sKeyG[lane];
            int r = 0;
            #pragma unroll
            for (int j2 = 0; j2 < 4; j2++) {
                float kj = sKeyG[j2];
                r += (kj < ki) || (kj == ki && j2 < lane);
            }
            sG[r] = sGT[lane];
        }
    }
    __syncthreads();

    if (w == 0) {
        int c = hull_finish_warp(sP9, 9, sHa, sKeyA, sVa, lane);
        if (lane == 0) {
            s_apred = shoelace16(sVa, c);
            float sgt = 0.f;
            #pragma unroll
            for (int i = 0; i < 4; i++) {
                int nx = (i + 1 < 4) ? i + 1 : 0;
                sgt = __fadd_rn(sgt, cross_nf(sG[i].x, sG[i].y, sG[nx].x, sG[nx].y));
            }
            s_agt = 0.5f * fabsf(sgt);
        }
        for (int e = 0; e < 4; e++) clip_warp(sVa, c, sG[e], sG[(e + 1) & 3], lane, sScrA);
        if (lane == 0) s_aint = shoelace16(sVa, c);
    } else if (w == 1) {
        int ch = hull_finish_warp(sPtsB, 13, sHb, sKeyB, sVb, lane);
        if (lane == 0) s_ahull = shoelace16(sVb, ch);
    } else if (w == 2) {
        float val = 0.f;
        if (lane < 9) {
            float mx = -f_inf();
            #pragma unroll
            for (int e = 0; e < 4; e++) {
                float ex = __fsub_rn(sG[(e + 1) & 3].x, sG[e].x);
                float ey = __fsub_rn(sG[(e + 1) & 3].y, sG[e].y);
                float num = cross_nf(ex, ey, __fsub_rn(sP9[lane].x, sG[e].x),
                                             __fsub_rn(sP9[lane].y, sG[e].y));
                float sv = __fdiv_rn(num,
                    __fadd_rn(__fsqrt_rn(__fadd_rn(__fmul_rn(ex, ex),
                                                   __fmul_rn(ey, ey))), 1e-9f));
                mx = fmaxf(mx, -sv);
            }
            val = fmaxf(mx, 0.f);
        }
        float acc = 0.f;
        #pragma unroll
        for (int p = 0; p < 9; p++) {
            float vp = __shfl_sync(FULLM, val, p);
            acc = __fadd_rn(acc, vp);
        }
        if (lane == 0) s_oob = __fdiv_rn(acc, 9.0f);
    }
    __syncthreads();

    if (tid == 0) {
        float uni = __fsub_rn(__fadd_rn(s_apred, s_agt), s_aint);
        float iou = __fdiv_rn(s_aint, __fadd_rn(uni, 1e-16f));
        float giou = __fsub_rn(iou, __fdiv_rn(__fsub_rn(s_ahull, uni),
                                              __fadd_rn(s_ahull, 1e-16f)));
        g_task_gl[s][m]  = (double)__fsub_rn(1.0f, giou);
        g_task_oob[s][m] = (double)s_oob;
    }
}

// ================= kernel 3: final combine + state restore =================
__global__ void k_final(int N, float* __restrict__ out)
{
    __shared__ double s_tgl[2 * KMAX], s_tob[2 * KMAX];
    __shared__ double s_lse[NAS];
    const int tid = threadIdx.x;
    const int nt  = blockDim.x;

    int c0 = __ldcg(&g_cnt01[0]);
    int c1 = __ldcg(&g_cnt01[1]);
    for (int q = tid; q < 2 * KMAX; q += nt) {
        int s2 = q >> 6, mm = q & 63;
        int cs = s2 ? c1 : c0;
        s_tgl[q] = (mm < cs) ? __ldcg(&g_task_gl[s2][mm])  : 0.0;
        s_tob[q] = (mm < cs) ? __ldcg(&g_task_oob[s2][mm]) : 0.0;
    }
    for (int q = tid; q < NAS; q += nt) s_lse[q] = __ldcg(&g_blk_lse[q]);
    __syncthreads();
    if (tid == 0) {
        double lse = 0.0;
        for (int q = 0; q < NAS; q++) lse += s_lse[q];             // fixed order
        double loc_i = 0.0, sc_i = 0.0, loc_r = 0.0, sc_r = 0.0;
        for (int mm = 0; mm < KMAX; mm++) { loc_i += s_tgl[mm];        sc_i += s_tob[mm]; }
        for (int mm = 0; mm < KMAX; mm++) { loc_r += s_tgl[KMAX + mm]; sc_r += s_tob[KMAX + mm]; }
        double corr = __ldcg(&g_corr_val);
        double cls_loss = (lse + corr) / (double)N;
        double ni = (double)max(c0, 1);
        double nr = (double)max(c1, 1);
        double loss = cls_loss
                    + 0.3  * (loc_i / ni)
                    + 1.0  * (loc_r / nr)
                    + 0.05 * (sc_i / ni)
                    + 0.1  * (sc_r / nr);
        out[0] = (float)loss;
    }
    // restore zero-init g_best for the next (identical) launch
    for (int q = tid; q < NB; q += nt) { g_best[0][q] = 0ull; g_best[1][q] = 0ull; }
}

// ---------------- launch ----------------
extern "C" void kernel_launch(void* const* d_in, const int* in_sizes, int n_in,
                              void* d_out, int out_size)
{
    const float* rpi  = (const float*)d_in[0];
    const float* rpr  = (const float*)d_in[1];
    const float* cls  = (const float*)d_in[2];
    const float* pstr = (const float*)d_in[3];
    const float* gtb  = (const float*)d_in[4];
    const int*   glab = (const int*)d_in[5];
    float* out = (float*)d_out;

    int N = in_sizes[3];          // points_stride element count
    int K = in_sizes[5];          // gt_labels element count (=64)
    if (K > KMAX) K = KMAX;

    k_assign<<<NAS, NTHR>>>(rpi, rpr, cls, pstr, gtb, N, K);
    k_tasks<<<2 * KMAX, NTHR>>>(rpi, rpr, cls, gtb, glab, K);
    k_final<<<1, 256>>>(N, out);
}

// round 11
// speedup vs baseline: 1.0337x; 1.0337x over previous
#include <cuda_runtime.h>
#include <math.h>
#include <stdint.h>

#define KMAX 64
#define BUF  16
#define NLVL 5          // levels 3..7
#define NB   (NLVL * KMAX)
#define NAS  148        // assign grid = SM count
#define NTHR_A 512      // assign block
#define NTHR 1024       // tasks block
#define FULLM 0xffffffffu

// ---------------- device-global state (zero-init; g_best restored by k_final) ----------------
__device__ unsigned long long g_best[2][NB];     // INVERTED packed keys; 0 = empty (max-reduced)
__device__ int    g_k2b[KMAX];                   // original k -> bucket slot
__device__ int    g_cnt01[2];
__device__ double g_blk_lse[NAS];
__device__ double g_corr_val;
__device__ double g_task_gl[2][KMAX];
__device__ double g_task_oob[2][KMAX];

__device__ __forceinline__ float f_inf() { return __int_as_float(0x7f800000); }

// Non-FMA cross product: matches XLA's unfused mul/sub semantics exactly.
__device__ __forceinline__ float cross_nf(float ax, float ay, float bx, float by)
{
    return __fsub_rn(__fmul_rn(ax, by), __fmul_rn(ay, bx));
}

// ---------------- geometry helpers (bit-identical to prior passing rounds) ----------------
__device__ float shoelace16(const float2* V, int c)
{
    float s = 0.f;
    #pragma unroll
    for (int i = 0; i < BUF; i++) {
        if (i >= c) continue;
        int nxt = (i + 1 < c) ? i + 1 : 0;
        s = __fadd_rn(s, cross_nf(V[i].x, V[i].y, V[nxt].x, V[nxt].y));
    }
    return 0.5f * fabsf(s);
}

__device__ __forceinline__ int hull_member_warp(const float2* pts, int n, int i, int lane)
{
    bool flag = false;
    if (lane < n && lane != i) {
        float pix = pts[i].x, piy = pts[i].y;
        float dx = __fsub_rn(pts[lane].x, pix), dy = __fsub_rn(pts[lane].y, piy);
        float mn = f_inf();
        for (int k = 0; k < n; k++) {
            float cr = cross_nf(dx, dy, __fsub_rn(pts[k].x, pix), __fsub_rn(pts[k].y, piy));
            mn = fminf(mn, cr);
        }
        flag = (mn >= -1e-6f);
    }
    return __ballot_sync(FULLM, flag) != 0;
}

__device__ int hull_finish_warp(const float2* pts, int n, const int* hflag,
                                float* skey, float2* sV, int lane)
{
    bool hf = (lane < n) ? (hflag[lane] != 0) : false;
    unsigned mask = __ballot_sync(FULLM, hf);
    int cnt = __popc(mask);
    float sx = 0.f, sy = 0.f;
    for (int i = 0; i < n; i++)
        if ((mask >> i) & 1) { sx = __fadd_rn(sx, pts[i].x); sy = __fadd_rn(sy, pts[i].y); }
    float cd = (float)(cnt > 0 ? cnt : 1);
    float cenx = __fdiv_rn(sx, cd), ceny = __fdiv_rn(sy, cd);
    if (lane < n)
        skey[lane] = hf ? atan2f(__fsub_rn(pts[lane].y, ceny), __fsub_rn(pts[lane].x, cenx))
                        : f_inf();
    __syncwarp();
    if (lane < n) {
        float ki = skey[lane];
        int r = 0;
        for (int j = 0; j < n; j++) {
            float kj = skey[j];
            r += (kj < ki) || (kj == ki && j < lane);   // stable rank == argsort
        }
        sV[r] = pts[lane];
    }
    if (lane >= n && lane < BUF) sV[lane] = make_float2(0.f, 0.f);
    __syncwarp();
    return cnt;
}

__device__ void clip_warp(float2* V, int& c, float2 a, float2 b, int lane, float2* scratch)
{
    float ex = __fsub_rn(b.x, a.x), ey = __fsub_rn(b.y, a.y);
    int cc = c;
    bool active = (lane < BUF) && (lane < cc);
    int nxt = (lane + 1 < cc) ? lane + 1 : 0;
    float2 cur = active ? V[lane] : make_float2(0.f, 0.f);
    float2 nx  = active ? V[nxt]  : make_float2(0.f, 0.f);
    float s_cur = cross_nf(ex, ey, __fsub_rn(cur.x, a.x), __fsub_rn(cur.y, a.y));
    float s_nxt = cross_nf(ex, ey, __fsub_rn(nx.x,  a.x), __fsub_rn(nx.y,  a.y));
    bool in_cur = s_cur >= 0.f, in_nxt = s_nxt >= 0.f;
    float den = __fsub_rn(s_cur, s_nxt);
    float t = (fabsf(den) > 1e-9f) ? __fdiv_rn(s_cur, den) : 0.f;
    float2 ipt = make_float2(__fadd_rn(cur.x, __fmul_rn(t, __fsub_rn(nx.x, cur.x))),
                             __fadd_rn(cur.y, __fmul_rn(t, __fsub_rn(nx.y, cur.y))));
    bool f_int = active && (in_cur != in_nxt);
    bool f_nxt = active && in_nxt;
    unsigned bi = __ballot_sync(FULLM, f_int);
    unsigned bn = __ballot_sync(FULLM, f_nxt);
    unsigned below = (1u << lane) - 1u;
    int pos_i = __popc(bi & below) + __popc(bn & below);
    int pos_n = pos_i + (f_int ? 1 : 0);
    int nc = __popc(bi) + __popc(bn);
    __syncwarp();
    if (f_int && pos_i < BUF) scratch[pos_i] = ipt;
    if (f_nxt && pos_n < BUF) scratch[pos_n] = nx;
    __syncwarp();
    if (lane < BUF) V[lane] = (lane < nc) ? scratch[lane] : make_float2(0.f, 0.f);
    __syncwarp();
    c = nc;
}

// ---------------- assign helper: one point's gt loop (warp-aggregated) ----------------
__device__ __forceinline__ void assign_point(
    bool act, float2 pi, float2 pr, unsigned un, int li,
    const float4* s_bkt, const int* s_cnt, int lane)
{
    unsigned actmask = __ballot_sync(FULLM, act);
    if (!actmask) return;
    int src = __ffs(actmask) - 1;
    int uli = __shfl_sync(FULLM, li, src);
    bool uniform = __all_sync(FULLM, !act || (li == uli));
    if (uniform) {
        int cnt = s_cnt[uli], base = uli * KMAX;
        for (int m = 0; m < cnt; m++) {
            int slot = base + m;
            float4 gq = s_bkt[slot];
            unsigned long long ki = 0ull, kr = 0ull;
            if (act) {
                float dxi = __fmul_rn(__fsub_rn(pi.x, gq.x), gq.z);
                float dyi = __fmul_rn(__fsub_rn(pi.y, gq.y), gq.w);
                float ddi = __fadd_rn(__fmul_rn(dxi, dxi), __fmul_rn(dyi, dyi));
                ki = ~(((unsigned long long)__float_as_uint(ddi) << 32) | un);
                float dxr = __fmul_rn(__fsub_rn(pr.x, gq.x), gq.z);
                float dyr = __fmul_rn(__fsub_rn(pr.y, gq.y), gq.w);
                float ddr = __fadd_rn(__fmul_rn(dxr, dxr), __fmul_rn(dyr, dyr));
                kr = ~(((unsigned long long)__float_as_uint(ddr) << 32) | un);
            }
            #pragma unroll
            for (int o = 16; o; o >>= 1) {
                unsigned long long ti = __shfl_down_sync(FULLM, ki, o);
                unsigned long long tr = __shfl_down_sync(FULLM, kr, o);
                if (ti > ki) ki = ti;
                if (tr > kr) kr = tr;
            }
            if (lane == 0) {
                if (ki) atomicMax(&g_best[0][slot], ki);
                if (kr) atomicMax(&g_best[1][slot], kr);
            }
        }
    } else if (act) {
        int cnt = s_cnt[li], base = li * KMAX;
        for (int m = 0; m < cnt; m++) {
            int slot = base + m;
            float4 gq = s_bkt[slot];
            float dxi = __fmul_rn(__fsub_rn(pi.x, gq.x), gq.z);
            float dyi = __fmul_rn(__fsub_rn(pi.y, gq.y), gq.w);
            float ddi = __fadd_rn(__fmul_rn(dxi, dxi), __fmul_rn(dyi, dyi));
            atomicMax(&g_best[0][slot], ~(((unsigned long long)__float_as_uint(ddi) << 32) | un));
            float dxr = __fmul_rn(__fsub_rn(pr.x, gq.x), gq.z);
            float dyr = __fmul_rn(__fsub_rn(pr.y, gq.y), gq.w);
            float ddr = __fadd_rn(__fmul_rn(dxr, dxr), __fmul_rn(dyr, dyr));
            atomicMax(&g_best[1][slot], ~(((unsigned long long)__float_as_uint(ddr) << 32) | un));
        }
    }
}

__device__ __forceinline__ double lse_term(const float4* c4q)
{
    float v[16];
    #pragma unroll
    for (int j = 0; j < 4; j++) {
        float4 f = c4q[j];
        v[4 * j] = f.x; v[4 * j + 1] = f.y; v[4 * j + 2] = f.z; v[4 * j + 3] = f.w;
    }
    float mm = v[0];
    #pragma unroll
    for (int j = 1; j < 16; j++) mm = fmaxf(mm, v[j]);
    float ss = 0.f;
    #pragma unroll
    for (int j = 0; j < 16; j++) ss += __expf(v[j] - mm);
    return (double)((mm + __logf(ss)) - v[0]);
}

// ================= kernel 1: prep + assign + cls logsumexp =================
// All 148 SMs active: block bid owns points [bid*C, bid*C+C). 2 points/thread,
// ALL loads hoisted (clamped addresses) so DRAM streams while gt loops compute.
__global__ void __launch_bounds__(NTHR_A, 1) k_assign(
    const float* __restrict__ rpi, const float* __restrict__ rpr,
    const float* __restrict__ cls, const float* __restrict__ pstr,
    const float* __restrict__ gtb, int N, int K, int C)
{
    __shared__ float  s_cx[KMAX], s_cy[KMAX], s_rw[KMAX], s_rh[KMAX];
    __shared__ int    s_lvl[KMAX];
    __shared__ float4 s_bkt[NB];
    __shared__ int    s_k2b[KMAX];
    __shared__ int    s_cnt[NLVL];
    __shared__ double s_red[NTHR_A / 32];

    const int tid  = threadIdx.x;
    const int bid  = blockIdx.x;
    const int lane = tid & 31;
    const int w    = tid >> 5;

    if (tid < K) {
        const float* r = gtb + 8 * tid;
        float xmn = fminf(fminf(r[0], r[2]), fminf(r[4], r[6]));
        float xmx = fmaxf(fmaxf(r[0], r[2]), fmaxf(r[4], r[6]));
        float ymn = fminf(fminf(r[1], r[3]), fminf(r[5], r[7]));
        float ymx = fmaxf(fmaxf(r[1], r[3]), fmaxf(r[5], r[7]));
        float ww = fmaxf(__fsub_rn(xmx, xmn), 1e-6f);
        float hh = fmaxf(__fsub_rn(ymx, ymn), 1e-6f);
        s_cx[tid] = __fmul_rn(__fadd_rn(xmn, xmx), 0.5f);
        s_cy[tid] = __fmul_rn(__fadd_rn(ymn, ymx), 0.5f);
        s_rw[tid] = __fdiv_rn(1.0f, ww);
        s_rh[tid] = __fdiv_rn(1.0f, hh);
        float lv = __fmul_rn(__fadd_rn(log2f(__fdiv_rn(ww, 4.0f)),
                                       log2f(__fdiv_rn(hh, 4.0f))), 0.5f);
        int lvl = (int)lv;
        s_lvl[tid] = max(3, min(7, lvl));
    }
    __syncthreads();
    if (tid == 0) {                                  // serial bucket build, ascending k
        int cnt[NLVL];
        #pragma unroll
        for (int l = 0; l < NLVL; l++) cnt[l] = 0;
        for (int q = 0; q < K; q++) {
            int li = s_lvl[q] - 3;
            int slot = li * KMAX + cnt[li];
            s_bkt[slot] = make_float4(s_cx[q], s_cy[q], s_rw[q], s_rh[q]);
            s_k2b[q] = slot;
            cnt[li]++;
        }
        #pragma unroll
        for (int l = 0; l < NLVL; l++) s_cnt[l] = cnt[l];
    }
    __syncthreads();
    if (bid == 0 && tid < K) g_k2b[tid] = s_k2b[tid];   // publish map for k_tasks

    const int base = bid * C;
    const int n1 = base + tid;
    const int n2 = base + NTHR_A + tid;
    const bool a1 = (tid < C) && (n1 < N);
    const bool a2 = (NTHR_A + tid < C) && (n2 < N);
    const int i1 = a1 ? n1 : 0;
    const int i2 = a2 ? n2 : 0;

    // hoisted loads: everything issues up front, overlapping the gt loops below
    float  st1 = __ldg(pstr + i1);
    float  st2 = __ldg(pstr + i2);
    float2 pi1 = __ldg((const float2*)(rpi + (size_t)i1 * 18 + 8));
    float2 pr1 = __ldg((const float2*)(rpr + (size_t)i1 * 18 + 8));
    float2 pi2 = __ldg((const float2*)(rpi + (size_t)i2 * 18 + 8));
    float2 pr2 = __ldg((const float2*)(rpr + (size_t)i2 * 18 + 8));
    float4 c1[4], c2[4];
    {
        const float4* q1 = (const float4*)(cls + (size_t)i1 * 16);
        const float4* q2 = (const float4*)(cls + (size_t)i2 * 16);
        #pragma unroll
        for (int j = 0; j < 4; j++) { c1[j] = __ldg(q1 + j); c2[j] = __ldg(q2 + j); }
    }
    int li1 = (31 - __clz((int)st1)) - 3;
    int li2 = (31 - __clz((int)st2)) - 3;

    assign_point(a1, pi1, pr1, (unsigned)n1, li1, s_bkt, s_cnt, lane);
    assign_point(a2, pi2, pr2, (unsigned)n2, li2, s_bkt, s_cnt, lane);

    // safety fallback for C > 2*NTHR_A (not taken for this dataset)
    for (int off = 2 * NTHR_A; off + tid < C; off += NTHR_A) {
        int n = base + off + tid;
        if (n < N) {
            int li = (31 - __clz((int)__ldg(pstr + n))) - 3;
            float2 pi = __ldg((const float2*)(rpi + (size_t)n * 18 + 8));
            float2 pr = __ldg((const float2*)(rpr + (size_t)n * 18 + 8));
            assign_point(true, pi, pr, (unsigned)n, li, s_bkt, s_cnt, lane);
        } else {
            assign_point(false, make_float2(0.f, 0.f), make_float2(0.f, 0.f), 0u, 0,
                         s_bkt, s_cnt, lane);
        }
    }

    double lterm = 0.0;
    if (a1) lterm += lse_term(c1);
    if (a2) lterm += lse_term(c2);
    for (int off = 2 * NTHR_A; off + tid < C; off += NTHR_A) {
        int n = base + off + tid;
        if (n < N) lterm += lse_term((const float4*)(cls + (size_t)n * 16));
    }
    for (int o = 16; o; o >>= 1) lterm += __shfl_down_sync(FULLM, lterm, o);
    if (lane == 0) s_red[w] = lterm;
    __syncthreads();
    if (tid == 0) {
        double bs = 0.0;
        for (int q = 0; q < NTHR_A / 32; q++) bs += s_red[q];
        g_blk_lse[bid] = bs;
    }
}

// ================= kernel 2: per-block replay + corr + geometry =================
__global__ void __launch_bounds__(NTHR, 1) k_tasks(
    const float* __restrict__ rpi, const float* __restrict__ rpr,
    const float* __restrict__ cls, const float* __restrict__ gtb,
    const int* __restrict__ glab, int K)
{
    __shared__ unsigned long long s_cmp[KMAX];
    __shared__ int s_j[KMAX];
    __shared__ int s_lead[KMAX];
    __shared__ int s_pidx[KMAX], s_pgt[KMAX];
    __shared__ int s_npos;
    __shared__ double s_red[32];
    __shared__ float2 sP9[9];
    __shared__ float2 sGT[4];
    __shared__ float2 sG[4];
    __shared__ float2 sPtsB[13];
    __shared__ int    sHa[9], sHb[13];
    __shared__ float2 sVa[BUF], sVb[BUF];
    __shared__ float2 sScrA[BUF];
    __shared__ float  sKeyA[13], sKeyB[13], sKeyG[4];
    __shared__ float  s_apred, s_agt, s_aint, s_ahull, s_oob;

    const int tid  = threadIdx.x;
    const int bid  = blockIdx.x;
    const int lane = tid & 31;
    const int w    = tid >> 5;
    const int s = (bid >= KMAX) ? 1 : 0;
    const int m = bid - s * KMAX;

    if (tid < KMAX) {
        unsigned long long v = (tid < K) ? __ldcg(&g_best[s][__ldg(&g_k2b[tid])]) : 0ull;
        bool valid = (v != 0ull);
        unsigned long long pk = ~v;              // (md_bits<<32)|point_idx
        s_j[tid]   = valid ? (int)(unsigned)(pk & 0xffffffffu) : (-1 - tid);
        s_cmp[tid] = valid ? (((pk >> 32) << 32) | (unsigned)tid) : ~0ull;
    }
    __syncthreads();
    if (tid < KMAX) {
        int j = s_j[tid];
        bool lead = (j >= 0);
        if (lead)
            for (int e = 0; e < tid; e++)
                if (s_j[e] == j) { lead = false; break; }
        s_lead[tid] = lead ? 1 : 0;
    }
    __syncthreads();
    if (tid < K && s_lead[tid]) {
        int j = s_j[tid];
        unsigned long long best = s_cmp[tid];
        for (int e = 0; e < K; e++)
            if (s_j[e] == j && s_cmp[e] < best) best = s_cmp[e];
        int pos = 0;
        for (int e = 0; e < tid; e++) pos += s_lead[e];
        s_pidx[pos] = j;
        s_pgt[pos]  = (int)(unsigned)(best & 0xffffffffu);
    }
    __syncthreads();
    if (tid == 0) {
        int cnt = 0;
        for (int e = 0; e < K; e++) cnt += s_lead[e];
        s_npos = cnt;
        if (m == 0) g_cnt01[s] = cnt;            // blocks 0 and KMAX publish counts
    }
    __syncthreads();

    if (bid == KMAX) {
        double part = 0.0;
        if (tid < s_npos) {
            int j   = s_pidx[tid];
            int lab = glab[s_pgt[tid]];
            part = (double)cls[(size_t)j * 16 + 0] - (double)cls[(size_t)j * 16 + lab];
        }
        for (int o = 16; o; o >>= 1) part += __shfl_down_sync(FULLM, part, o);
        if (lane == 0) s_red[w] = part;
        __syncthreads();
        if (tid == 0) {
            double cs = 0.0;
            for (int q = 0; q < NTHR / 32; q++) cs += s_red[q];
            g_corr_val = cs;
        }
    }

    if (m >= s_npos) return;

    const float* rp  = s ? rpr : rpi;
    {
        int j  = s_pidx[m];
        int gi = s_pgt[m];
        const float* g8  = gtb + 8 * gi;
        const float* p18 = rp + (size_t)j * 18;
        if (tid < 4) {
            float2 c = make_float2(g8[2 * tid], g8[2 * tid + 1]);
            sGT[tid] = c;
            sPtsB[tid] = c;
        }
        if (tid >= 4 && tid < 13) {
            float2 c = make_float2(p18[2 * (tid - 4)], p18[2 * (tid - 4) + 1]);
            sP9[tid - 4] = c;
            sPtsB[tid] = c;
        }
    }
    __syncthreads();

    if (w < 13) {
        int h = hull_member_warp(sPtsB, 13, w, lane);
        if (lane == 0) sHb[w] = h;
    } else if (w >= 16 && w < 25) {
        int h = hull_member_warp(sP9, 9, w - 16, lane);
        if (lane == 0) sHa[w - 16] = h;
    } else if (w == 13) {
        if (lane < 4) {
            float cmx = (sGT[0].x + sGT[1].x + sGT[2].x + sGT[3].x) * 0.25f;
            float cmy = (sGT[0].y + sGT[1].y + sGT[2].y + sGT[3].y) * 0.25f;
            sKeyG[lane] = atan2f(__fsub_rn(sGT[lane].y, cmy),
                                 __fsub_rn(sGT[lane].x, cmx));
        }
        __syncwarp();
        if (lane < 4) {
            float ki = sKeyG[lane];
            int r = 0;
            #pragma unroll
            for (int j2 = 0; j2 < 4; j2++) {
                float kj = sKeyG[j2];
                r += (kj < ki) || (kj == ki && j2 < lane);
            }
            sG[r] = sGT[lane];
        }
    }
    __syncthreads();

    if (w == 0) {
        int c = hull_finish_warp(sP9, 9, sHa, sKeyA, sVa, lane);
        if (lane == 0) {
            s_apred = shoelace16(sVa, c);
            float sgt = 0.f;
            #pragma unroll
            for (int i = 0; i < 4; i++) {
                int nx = (i + 1 < 4) ? i + 1 : 0;
                sgt = __fadd_rn(sgt, cross_nf(sG[i].x, sG[i].y, sG[nx].x, sG[nx].y));
            }
            s_agt = 0.5f * fabsf(sgt);
        }
        for (int e = 0; e < 4; e++) clip_warp(sVa, c, sG[e], sG[(e + 1) & 3], lane, sScrA);
        if (lane == 0) s_aint = shoelace16(sVa, c);
    } else if (w == 1) {
        int ch = hull_finish_warp(sPtsB, 13, sHb, sKeyB, sVb, lane);
        if (lane == 0) s_ahull = shoelace16(sVb, ch);
    } else if (w == 2) {
        float val = 0.f;
        if (lane < 9) {
            float mx = -f_inf();
            #pragma unroll
            for (int e = 0; e < 4; e++) {
                float ex = __fsub_rn(sG[(e + 1) & 3].x, sG[e].x);
                float ey = __fsub_rn(sG[(e + 1) & 3].y, sG[e].y);
                float num = cross_nf(ex, ey, __fsub_rn(sP9[lane].x, sG[e].x),
                                             __fsub_rn(sP9[lane].y, sG[e].y));
                float sv = __fdiv_rn(num,
                    __fadd_rn(__fsqrt_rn(__fadd_rn(__fmul_rn(ex, ex),
                                                   __fmul_rn(ey, ey))), 1e-9f));
                mx = fmaxf(mx, -sv);
            }
            val = fmaxf(mx, 0.f);
        }
        float acc = 0.f;
        #pragma unroll
        for (int p = 0; p < 9; p++) {
            float vp = __shfl_sync(FULLM, val, p);
            acc = __fadd_rn(acc, vp);
        }
        if (lane == 0) s_oob = __fdiv_rn(acc, 9.0f);
    }
    __syncthreads();

    if (tid == 0) {
        float uni = __fsub_rn(__fadd_rn(s_apred, s_agt), s_aint);
        float iou = __fdiv_rn(s_aint, __fadd_rn(uni, 1e-16f));
        float giou = __fsub_rn(iou, __fdiv_rn(__fsub_rn(s_ahull, uni),
                                              __fadd_rn(s_ahull, 1e-16f)));
        g_task_gl[s][m]  = (double)__fsub_rn(1.0f, giou);
        g_task_oob[s][m] = (double)s_oob;
    }
}

// ================= kernel 3: final combine + state restore =================
__global__ void k_final(int N, float* __restrict__ out)
{
    __shared__ double s_tgl[2 * KMAX], s_tob[2 * KMAX];
    __shared__ double s_lse[NAS];
    const int tid = threadIdx.x;
    const int nt  = blockDim.x;

    int c0 = __ldcg(&g_cnt01[0]);
    int c1 = __ldcg(&g_cnt01[1]);
    for (int q = tid; q < 2 * KMAX; q += nt) {
        int s2 = q >> 6, mm = q & 63;
        int cs = s2 ? c1 : c0;
        s_tgl[q] = (mm < cs) ? __ldcg(&g_task_gl[s2][mm])  : 0.0;
        s_tob[q] = (mm < cs) ? __ldcg(&g_task_oob[s2][mm]) : 0.0;
    }
    for (int q = tid; q < NAS; q += nt) s_lse[q] = __ldcg(&g_blk_lse[q]);
    __syncthreads();
    if (tid == 0) {
        double lse = 0.0;
        for (int q = 0; q < NAS; q++) lse += s_lse[q];             // fixed order
        double loc_i = 0.0, sc_i = 0.0, loc_r = 0.0, sc_r = 0.0;
        for (int mm = 0; mm < KMAX; mm++) { loc_i += s_tgl[mm];        sc_i += s_tob[mm]; }
        for (int mm = 0; mm < KMAX; mm++) { loc_r += s_tgl[KMAX + mm]; sc_r += s_tob[KMAX + mm]; }
        double corr = __ldcg(&g_corr_val);
        double cls_loss = (lse + corr) / (double)N;
        double ni = (double)max(c0, 1);
        double nr = (double)max(c1, 1);
        double loss = cls_loss
                    + 0.3  * (loc_i / ni)
                    + 1.0  * (loc_r / nr)
                    + 0.05 * (sc_i / ni)
                    + 0.1  * (sc_r / nr);
        out[0] = (float)loss;
    }
    // restore zero-init g_best for the next (identical) launch
    for (int q = tid; q < NB; q += nt) { g_best[0][q] = 0ull; g_best[1][q] = 0ull; }
}

// ---------------- launch ----------------
extern "C" void kernel_launch(void* const* d_in, const int* in_sizes, int n_in,
                              void* d_out, int out_size)
{
    const float* rpi  = (const float*)d_in[0];
    const float* rpr  = (const float*)d_in[1];
    const float* cls  = (const float*)d_in[2];
    const float* pstr = (const float*)d_in[3];
    const float* gtb  = (const float*)d_in[4];
    const int*   glab = (const int*)d_in[5];
    float* out = (float*)d_out;

    int N = in_sizes[3];          // points_stride element count
    int K = in_sizes[5];          // gt_labels element count (=64)
    if (K > KMAX) K = KMAX;

    int C = ((N + NAS - 1) / NAS + 31) & ~31;   // points per assign block, 32-aligned

    k_assign<<<NAS, NTHR_A>>>(rpi, rpr, cls, pstr, gtb, N, K, C);
    k_tasks<<<2 * KMAX, NTHR>>>(rpi, rpr, cls, gtb, glab, K);
    k_final<<<1, 256>>>(N, out);
}

// round 12
// speedup vs baseline: 1.2589x; 1.2180x over previous
#include <cuda_runtime.h>
#include <math.h>
#include <stdint.h>

#define KMAX 64
#define BUF  16
#define NLVL 5          // levels 3..7
#define NB   (NLVL * KMAX)
#define NAS  148        // assign grid = SM count
#define NTHR_A 1024     // assign block
#define NTHR_T 800      // tasks block (25 warps used)
#define FULLM 0xffffffffu

// ---------------- device-global state (zero-init; g_best restored by k_final) ----------------
__device__ unsigned long long g_best[2][NB];     // INVERTED packed keys; 0 = empty (max-reduced)
__device__ int    g_k2b[KMAX];                   // original k -> bucket slot
__device__ int    g_cnt01[2];
__device__ double g_blk_lse[NAS];
__device__ double g_corr_val;
__device__ double g_task_gl[2][KMAX];
__device__ double g_task_oob[2][KMAX];

__device__ __forceinline__ float f_inf() { return __int_as_float(0x7f800000); }

// Non-FMA cross product: matches XLA's unfused mul/sub semantics exactly.
__device__ __forceinline__ float cross_nf(float ax, float ay, float bx, float by)
{
    return __fsub_rn(__fmul_rn(ax, by), __fmul_rn(ay, bx));
}

// ---------------- geometry helpers (bit-identical to prior passing rounds) ----------------
__device__ float shoelace16(const float2* V, int c)
{
    float s = 0.f;
    #pragma unroll
    for (int i = 0; i < BUF; i++) {
        if (i >= c) continue;
        int nxt = (i + 1 < c) ? i + 1 : 0;
        s = __fadd_rn(s, cross_nf(V[i].x, V[i].y, V[nxt].x, V[nxt].y));
    }
    return 0.5f * fabsf(s);
}

__device__ __forceinline__ int hull_member_warp(const float2* pts, int n, int i, int lane)
{
    bool flag = false;
    if (lane < n && lane != i) {
        float pix = pts[i].x, piy = pts[i].y;
        float dx = __fsub_rn(pts[lane].x, pix), dy = __fsub_rn(pts[lane].y, piy);
        float mn = f_inf();
        for (int k = 0; k < n; k++) {
            float cr = cross_nf(dx, dy, __fsub_rn(pts[k].x, pix), __fsub_rn(pts[k].y, piy));
            mn = fminf(mn, cr);
        }
        flag = (mn >= -1e-6f);
    }
    return __ballot_sync(FULLM, flag) != 0;
}

__device__ int hull_finish_warp(const float2* pts, int n, const int* hflag,
                                float* skey, float2* sV, int lane)
{
    bool hf = (lane < n) ? (hflag[lane] != 0) : false;
    unsigned mask = __ballot_sync(FULLM, hf);
    int cnt = __popc(mask);
    float sx = 0.f, sy = 0.f;
    for (int i = 0; i < n; i++)
        if ((mask >> i) & 1) { sx = __fadd_rn(sx, pts[i].x); sy = __fadd_rn(sy, pts[i].y); }
    float cd = (float)(cnt > 0 ? cnt : 1);
    float cenx = __fdiv_rn(sx, cd), ceny = __fdiv_rn(sy, cd);
    if (lane < n)
        skey[lane] = hf ? atan2f(__fsub_rn(pts[lane].y, ceny), __fsub_rn(pts[lane].x, cenx))
                        : f_inf();
    __syncwarp();
    if (lane < n) {
        float ki = skey[lane];
        int r = 0;
        for (int j = 0; j < n; j++) {
            float kj = skey[j];
            r += (kj < ki) || (kj == ki && j < lane);   // stable rank == argsort
        }
        sV[r] = pts[lane];
    }
    if (lane >= n && lane < BUF) sV[lane] = make_float2(0.f, 0.f);
    __syncwarp();
    return cnt;
}

__device__ void clip_warp(float2* V, int& c, float2 a, float2 b, int lane, float2* scratch)
{
    float ex = __fsub_rn(b.x, a.x), ey = __fsub_rn(b.y, a.y);
    int cc = c;
    bool active = (lane < BUF) && (lane < cc);
    int nxt = (lane + 1 < cc) ? lane + 1 : 0;
    float2 cur = active ? V[lane] : make_float2(0.f, 0.f);
    float2 nx  = active ? V[nxt]  : make_float2(0.f, 0.f);
    float s_cur = cross_nf(ex, ey, __fsub_rn(cur.x, a.x), __fsub_rn(cur.y, a.y));
    float s_nxt = cross_nf(ex, ey, __fsub_rn(nx.x,  a.x), __fsub_rn(nx.y,  a.y));
    bool in_cur = s_cur >= 0.f, in_nxt = s_nxt >= 0.f;
    float den = __fsub_rn(s_cur, s_nxt);
    float t = (fabsf(den) > 1e-9f) ? __fdiv_rn(s_cur, den) : 0.f;
    float2 ipt = make_float2(__fadd_rn(cur.x, __fmul_rn(t, __fsub_rn(nx.x, cur.x))),
                             __fadd_rn(cur.y, __fmul_rn(t, __fsub_rn(nx.y, cur.y))));
    bool f_int = active && (in_cur != in_nxt);
    bool f_nxt = active && in_nxt;
    unsigned bi = __ballot_sync(FULLM, f_int);
    unsigned bn = __ballot_sync(FULLM, f_nxt);
    unsigned below = (1u << lane) - 1u;
    int pos_i = __popc(bi & below) + __popc(bn & below);
    int pos_n = pos_i + (f_int ? 1 : 0);
    int nc = __popc(bi) + __popc(bn);
    __syncwarp();
    if (f_int && pos_i < BUF) scratch[pos_i] = ipt;
    if (f_nxt && pos_n < BUF) scratch[pos_n] = nx;
    __syncwarp();
    if (lane < BUF) V[lane] = (lane < nc) ? scratch[lane] : make_float2(0.f, 0.f);
    __syncwarp();
    c = nc;
}

__device__ __forceinline__ double lse_term(const float4* c4q)
{
    float v[16];
    #pragma unroll
    for (int j = 0; j < 4; j++) {
        float4 f = c4q[j];
        v[4 * j] = f.x; v[4 * j + 1] = f.y; v[4 * j + 2] = f.z; v[4 * j + 3] = f.w;
    }
    float mm = v[0];
    #pragma unroll
    for (int j = 1; j < 16; j++) mm = fmaxf(mm, v[j]);
    float ss = 0.f;
    #pragma unroll
    for (int j = 0; j < 16; j++) ss += __expf(v[j] - mm);
    return (double)((mm + __logf(ss)) - v[0]);
}

// ================= kernel 1: prep + assign + cls logsumexp =================
// Warp-aggregated argmin via REDUX: lanes hold consecutive n, so winner index
// = warp_n_base + ffs(ballot(dd==min)) - 1. Tie-break (lowest lane = lowest n)
// is bit-identical to the old packed (dd<<32|n) min-reduce.
__global__ void __launch_bounds__(NTHR_A, 1) k_assign(
    const float* __restrict__ rpi, const float* __restrict__ rpr,
    const float* __restrict__ cls, const float* __restrict__ pstr,
    const float* __restrict__ gtb, int N, int K)
{
    __shared__ float  s_cx[KMAX], s_cy[KMAX], s_rw[KMAX], s_rh[KMAX];
    __shared__ int    s_lvl[KMAX];
    __shared__ float4 s_bkt[NB];
    __shared__ int    s_k2b[KMAX];
    __shared__ int    s_cnt[NLVL];
    __shared__ double s_red[NTHR_A / 32];

    const int tid  = threadIdx.x;
    const int bid  = blockIdx.x;
    const int lane = tid & 31;
    const int w    = tid >> 5;

    if (tid < K) {
        const float* r = gtb + 8 * tid;
        float xmn = fminf(fminf(r[0], r[2]), fminf(r[4], r[6]));
        float xmx = fmaxf(fmaxf(r[0], r[2]), fmaxf(r[4], r[6]));
        float ymn = fminf(fminf(r[1], r[3]), fminf(r[5], r[7]));
        float ymx = fmaxf(fmaxf(r[1], r[3]), fmaxf(r[5], r[7]));
        float ww = fmaxf(__fsub_rn(xmx, xmn), 1e-6f);
        float hh = fmaxf(__fsub_rn(ymx, ymn), 1e-6f);
        s_cx[tid] = __fmul_rn(__fadd_rn(xmn, xmx), 0.5f);
        s_cy[tid] = __fmul_rn(__fadd_rn(ymn, ymx), 0.5f);
        s_rw[tid] = __fdiv_rn(1.0f, ww);
        s_rh[tid] = __fdiv_rn(1.0f, hh);
        float lv = __fmul_rn(__fadd_rn(log2f(__fdiv_rn(ww, 4.0f)),
                                       log2f(__fdiv_rn(hh, 4.0f))), 0.5f);
        int lvl = (int)lv;
        s_lvl[tid] = max(3, min(7, lvl));
    }
    __syncthreads();
    if (tid == 0) {                                  // serial bucket build, ascending k
        int cnt[NLVL];
        #pragma unroll
        for (int l = 0; l < NLVL; l++) cnt[l] = 0;
        for (int q = 0; q < K; q++) {
            int li = s_lvl[q] - 3;
            int slot = li * KMAX + cnt[li];
            s_bkt[slot] = make_float4(s_cx[q], s_cy[q], s_rw[q], s_rh[q]);
            s_k2b[q] = slot;
            cnt[li]++;
        }
        #pragma unroll
        for (int l = 0; l < NLVL; l++) s_cnt[l] = cnt[l];
    }
    __syncthreads();
    if (bid == 0 && tid < K) g_k2b[tid] = s_k2b[tid];   // publish map for k_tasks

    double lterm = 0.0;
    for (int n = bid * NTHR_A + tid; n - tid < N; n += NAS * NTHR_A) {
        const bool act = (n < N);
        const int i0 = act ? n : 0;

        // hoisted loads (clamped): stream while the gt loop computes
        float  st = __ldg(pstr + i0);
        float2 pi = __ldg((const float2*)(rpi + (size_t)i0 * 18 + 8));
        float2 pr = __ldg((const float2*)(rpr + (size_t)i0 * 18 + 8));
        float4 cq[4];
        {
            const float4* q = (const float4*)(cls + (size_t)i0 * 16);
            #pragma unroll
            for (int j = 0; j < 4; j++) cq[j] = __ldg(q + j);
        }
        int li = (31 - __clz((int)st)) - 3;

        unsigned actmask = __ballot_sync(FULLM, act);
        if (actmask) {
            int src0 = __ffs(actmask) - 1;
            int uli = __shfl_sync(FULLM, li, src0);
            bool uniform = __all_sync(FULLM, !act || (li == uli));
            unsigned warp_n0 = (unsigned)(n - lane);     // consecutive n within warp
            if (uniform) {
                int cnt = s_cnt[uli], base = uli * KMAX;
                for (int m = 0; m < cnt; m++) {
                    int slot = base + m;
                    float4 gq = s_bkt[slot];
                    unsigned di = 0xffffffffu, dr = 0xffffffffu;
                    if (act) {
                        float dxi = __fmul_rn(__fsub_rn(pi.x, gq.x), gq.z);
                        float dyi = __fmul_rn(__fsub_rn(pi.y, gq.y), gq.w);
                        di = __float_as_uint(__fadd_rn(__fmul_rn(dxi, dxi), __fmul_rn(dyi, dyi)));
                        float dxr = __fmul_rn(__fsub_rn(pr.x, gq.x), gq.z);
                        float dyr = __fmul_rn(__fsub_rn(pr.y, gq.y), gq.w);
                        dr = __float_as_uint(__fadd_rn(__fmul_rn(dxr, dxr), __fmul_rn(dyr, dyr)));
                    }
                    unsigned mi = __reduce_min_sync(FULLM, di);
                    unsigned mr = __reduce_min_sync(FULLM, dr);
                    unsigned bi = __ballot_sync(FULLM, di == mi);
                    unsigned br = __ballot_sync(FULLM, dr == mr);
                    if (lane == 0) {
                        unsigned uni_ = warp_n0 + (unsigned)(__ffs(bi) - 1);
                        unsigned unr_ = warp_n0 + (unsigned)(__ffs(br) - 1);
                        atomicMax(&g_best[0][slot], ~(((unsigned long long)mi << 32) | uni_));
                        atomicMax(&g_best[1][slot], ~(((unsigned long long)mr << 32) | unr_));
                    }
                }
            } else if (act) {                            // level-boundary warps (rare)
                int cnt = s_cnt[li], base = li * KMAX;
                unsigned un = (unsigned)n;
                for (int m = 0; m < cnt; m++) {
                    int slot = base + m;
                    float4 gq = s_bkt[slot];
                    float dxi = __fmul_rn(__fsub_rn(pi.x, gq.x), gq.z);
                    float dyi = __fmul_rn(__fsub_rn(pi.y, gq.y), gq.w);
                    float ddi = __fadd_rn(__fmul_rn(dxi, dxi), __fmul_rn(dyi, dyi));
                    atomicMax(&g_best[0][slot],
                              ~(((unsigned long long)__float_as_uint(ddi) << 32) | un));
                    float dxr = __fmul_rn(__fsub_rn(pr.x, gq.x), gq.z);
                    float dyr = __fmul_rn(__fsub_rn(pr.y, gq.y), gq.w);
                    float ddr = __fadd_rn(__fmul_rn(dxr, dxr), __fmul_rn(dyr, dyr));
                    atomicMax(&g_best[1][slot],
                              ~(((unsigned long long)__float_as_uint(ddr) << 32) | un));
                }
            }
        }
        if (act) lterm += lse_term(cq);
    }
    for (int o = 16; o; o >>= 1) lterm += __shfl_down_sync(FULLM, lterm, o);
    if (lane == 0) s_red[w] = lterm;
    __syncthreads();
    if (tid == 0) {
        double bs = 0.0;
        for (int q = 0; q < NTHR_A / 32; q++) bs += s_red[q];
        g_blk_lse[bid] = bs;
    }
}

// ================= kernel 2: per-block replay + corr + geometry =================
__global__ void __launch_bounds__(NTHR_T, 1) k_tasks(
    const float* __restrict__ rpi, const float* __restrict__ rpr,
    const float* __restrict__ cls, const float* __restrict__ gtb,
    const int* __restrict__ glab, int K)
{
    __shared__ unsigned long long s_cmp[KMAX];
    __shared__ int s_j[KMAX];
    __shared__ int s_lead[KMAX];
    __shared__ int s_pidx[KMAX], s_pgt[KMAX];
    __shared__ int s_npos;
    __shared__ double s_red[32];
    __shared__ float2 sP9[9];
    __shared__ float2 sGT[4];
    __shared__ float2 sG[4];
    __shared__ float2 sPtsB[13];
    __shared__ int    sHa[9], sHb[13];
    __shared__ float2 sVa[BUF], sVb[BUF];
    __shared__ float2 sScrA[BUF];
    __shared__ float  sKeyA[13], sKeyB[13], sKeyG[4];
    __shared__ float  s_apred, s_agt, s_aint, s_ahull, s_oob;

    const int tid  = threadIdx.x;
    const int bid  = blockIdx.x;
    const int lane = tid & 31;
    const int w    = tid >> 5;
    const int s = (bid >= KMAX) ? 1 : 0;
    const int m = bid - s * KMAX;

    if (tid < KMAX) {
        unsigned long long v = (tid < K) ? __ldcg(&g_best[s][__ldg(&g_k2b[tid])]) : 0ull;
        bool valid = (v != 0ull);
        unsigned long long pk = ~v;              // (md_bits<<32)|point_idx
        s_j[tid]   = valid ? (int)(unsigned)(pk & 0xffffffffu) : (-1 - tid);
        s_cmp[tid] = valid ? (((pk >> 32) << 32) | (unsigned)tid) : ~0ull;
    }
    __syncthreads();
    if (tid < KMAX) {
        int j = s_j[tid];
        bool lead = (j >= 0);
        if (lead)
            for (int e = 0; e < tid; e++)
                if (s_j[e] == j) { lead = false; break; }
        s_lead[tid] = lead ? 1 : 0;
    }
    __syncthreads();
    if (tid < K && s_lead[tid]) {
        int j = s_j[tid];
        unsigned long long best = s_cmp[tid];
        for (int e = 0; e < K; e++)
            if (s_j[e] == j && s_cmp[e] < best) best = s_cmp[e];
        int pos = 0;
        for (int e = 0; e < tid; e++) pos += s_lead[e];
        s_pidx[pos] = j;
        s_pgt[pos]  = (int)(unsigned)(best & 0xffffffffu);
    }
    __syncthreads();
    if (tid == 0) {
        int cnt = 0;
        for (int e = 0; e < K; e++) cnt += s_lead[e];
        s_npos = cnt;
        if (m == 0) g_cnt01[s] = cnt;            // blocks 0 and KMAX publish counts
    }
    __syncthreads();

    if (bid == KMAX) {
        double part = 0.0;
        if (tid < s_npos) {
            int j   = s_pidx[tid];
            int lab = glab[s_pgt[tid]];
            part = (double)cls[(size_t)j * 16 + 0] - (double)cls[(size_t)j * 16 + lab];
        }
        for (int o = 16; o; o >>= 1) part += __shfl_down_sync(FULLM, part, o);
        if (lane == 0) s_red[w] = part;
        __syncthreads();
        if (tid == 0) {
            double cs = 0.0;
            for (int q = 0; q < NTHR_T / 32; q++) cs += s_red[q];
            g_corr_val = cs;
        }
    }

    if (m >= s_npos) return;

    const float* rp  = s ? rpr : rpi;
    {
        int j  = s_pidx[m];
        int gi = s_pgt[m];
        const float* g8  = gtb + 8 * gi;
        const float* p18 = rp + (size_t)j * 18;
        if (tid < 4) {
            float2 c = make_float2(g8[2 * tid], g8[2 * tid + 1]);
            sGT[tid] = c;
            sPtsB[tid] = c;
        }
        if (tid >= 4 && tid < 13) {
            float2 c = make_float2(p18[2 * (tid - 4)], p18[2 * (tid - 4) + 1]);
            sP9[tid - 4] = c;
            sPtsB[tid] = c;
        }
    }
    __syncthreads();

    if (w < 13) {
        int h = hull_member_warp(sPtsB, 13, w, lane);
        if (lane == 0) sHb[w] = h;
    } else if (w >= 16 && w < 25) {
        int h = hull_member_warp(sP9, 9, w - 16, lane);
        if (lane == 0) sHa[w - 16] = h;
    } else if (w == 13) {
        if (lane < 4) {
            float cmx = (sGT[0].x + sGT[1].x + sGT[2].x + sGT[3].x) * 0.25f;
            float cmy = (sGT[0].y + sGT[1].y + sGT[2].y + sGT[3].y) * 0.25f;
            sKeyG[lane] = atan2f(__fsub_rn(sGT[lane].y, cmy),
                                 __fsub_rn(sGT[lane].x, cmx));
        }
        __syncwarp();
        if (lane < 4) {
            float ki = sKeyG[lane];
            int r = 0;
            #pragma unroll
            for (int j2 = 0; j2 < 4; j2++) {
                float kj = sKeyG[j2];
                r += (kj < ki) || (kj == ki && j2 < lane);
            }
            sG[r] = sGT[lane];
        }
    }
    __syncthreads();

    if (w == 0) {
        int c = hull_finish_warp(sP9, 9, sHa, sKeyA, sVa, lane);
        if (lane == 0) {
            s_apred = shoelace16(sVa, c);
            float sgt = 0.f;
            #pragma unroll
            for (int i = 0; i < 4; i++) {
                int nx = (i + 1 < 4) ? i + 1 : 0;
                sgt = __fadd_rn(sgt, cross_nf(sG[i].x, sG[i].y, sG[nx].x, sG[nx].y));
            }
            s_agt = 0.5f * fabsf(sgt);
        }
        for (int e = 0; e < 4; e++) clip_warp(sVa, c, sG[e], sG[(e + 1) & 3], lane, sScrA);
        if (lane == 0) s_aint = shoelace16(sVa, c);
    } else if (w == 1) {
        int ch = hull_finish_warp(sPtsB, 13, sHb, sKeyB, sVb, lane);
        if (lane == 0) s_ahull = shoelace16(sVb, ch);
    } else if (w == 2) {
        float val = 0.f;
        if (lane < 9) {
            float mx = -f_inf();
            #pragma unroll
            for (int e = 0; e < 4; e++) {
                float ex = __fsub_rn(sG[(e + 1) & 3].x, sG[e].x);
                float ey = __fsub_rn(sG[(e + 1) & 3].y, sG[e].y);
                float num = cross_nf(ex, ey, __fsub_rn(sP9[lane].x, sG[e].x),
                                             __fsub_rn(sP9[lane].y, sG[e].y));
                float sv = __fdiv_rn(num,
                    __fadd_rn(__fsqrt_rn(__fadd_rn(__fmul_rn(ex, ex),
                                                   __fmul_rn(ey, ey))), 1e-9f));
                mx = fmaxf(mx, -sv);
            }
            val = fmaxf(mx, 0.f);
        }
        float acc = 0.f;
        #pragma unroll
        for (int p = 0; p < 9; p++) {
            float vp = __shfl_sync(FULLM, val, p);
            acc = __fadd_rn(acc, vp);
        }
        if (lane == 0) s_oob = __fdiv_rn(acc, 9.0f);
    }
    __syncthreads();

    if (tid == 0) {
        float uni = __fsub_rn(__fadd_rn(s_apred, s_agt), s_aint);
        float iou = __fdiv_rn(s_aint, __fadd_rn(uni, 1e-16f));
        float giou = __fsub_rn(iou, __fdiv_rn(__fsub_rn(s_ahull, uni),
                                              __fadd_rn(s_ahull, 1e-16f)));
        g_task_gl[s][m]  = (double)__fsub_rn(1.0f, giou);
        g_task_oob[s][m] = (double)s_oob;
    }
}

// ================= kernel 3: final combine + state restore =================
__global__ void k_final(int N, float* __restrict__ out)
{
    __shared__ double s_tgl[2 * KMAX], s_tob[2 * KMAX];
    __shared__ double s_lse[NAS];
    const int tid = threadIdx.x;
    const int nt  = blockDim.x;

    int c0 = __ldcg(&g_cnt01[0]);
    int c1 = __ldcg(&g_cnt01[1]);
    for (int q = tid; q < 2 * KMAX; q += nt) {
        int s2 = q >> 6, mm = q & 63;
        int cs = s2 ? c1 : c0;
        s_tgl[q] = (mm < cs) ? __ldcg(&g_task_gl[s2][mm])  : 0.0;
        s_tob[q] = (mm < cs) ? __ldcg(&g_task_oob[s2][mm]) : 0.0;
    }
    for (int q = tid; q < NAS; q += nt) s_lse[q] = __ldcg(&g_blk_lse[q]);
    __syncthreads();
    if (tid == 0) {
        double lse = 0.0;
        for (int q = 0; q < NAS; q++) lse += s_lse[q];             // fixed order
        double loc_i = 0.0, sc_i = 0.0, loc_r = 0.0, sc_r = 0.0;
        for (int mm = 0; mm < KMAX; mm++) { loc_i += s_tgl[mm];        sc_i += s_tob[mm]; }
        for (int mm = 0; mm < KMAX; mm++) { loc_r += s_tgl[KMAX + mm]; sc_r += s_tob[KMAX + mm]; }
        double corr = __ldcg(&g_corr_val);
        double cls_loss = (lse + corr) / (double)N;
        double ni = (double)max(c0, 1);
        double nr = (double)max(c1, 1);
        double loss = cls_loss
                    + 0.3  * (loc_i / ni)
                    + 1.0  * (loc_r / nr)
                    + 0.05 * (sc_i / ni)
                    + 0.1  * (sc_r / nr);
        out[0] = (float)loss;
    }
    // restore zero-init g_best for the next (identical) launch
    for (int q = tid; q < NB; q += nt) { g_best[0][q] = 0ull; g_best[1][q] = 0ull; }
}

// ---------------- launch ----------------
extern "C" void kernel_launch(void* const* d_in, const int* in_sizes, int n_in,
                              void* d_out, int out_size)
{
    const float* rpi  = (const float*)d_in[0];
    const float* rpr  = (const float*)d_in[1];
    const float* cls  = (const float*)d_in[2];
    const float* pstr = (const float*)d_in[3];
    const float* gtb  = (const float*)d_in[4];
    const int*   glab = (const int*)d_in[5];
    float* out = (float*)d_out;

    int N = in_sizes[3];          // points_stride element count
    int K = in_sizes[5];          // gt_labels element count (=64)
    if (K > KMAX) K = KMAX;

    k_assign<<<NAS, NTHR_A>>>(rpi, rpr, cls, pstr, gtb, N, K);
    k_tasks<<<2 * KMAX, NTHR_T>>>(rpi, rpr, cls, gtb, glab, K);
    k_final<<<1, 256>>>(N, out);
}